// round 17
// baseline (speedup 1.0000x reference)
#include <cuda_runtime.h>
#include <cuda_fp16.h>

// Problem constants
#define CNUM  19
#define NPAIR 10            // class pairs per pixel (pair 9 = {18, dummy})
#define NB    32            // error bins over [0,1]
#define STRIDE 80           // words/class: nonfg bin b at [b] (b<=32); fg bin b at [40+b]
#define NREP  16            // histogram replicas
#define HW    262144        // 512*512
#define PTOT  1048576       // 4*512*512

// [replica][class][80]; zero-init at load; loss_kernel re-zeroes.
__device__ __align__(16) unsigned g_hist[NREP * CNUM * STRIDE];
__device__ float    g_lossc[CNUM];
__device__ unsigned g_gts[CNUM];
__device__ unsigned g_done;          // completion counter (wraps to 0 each run)

__device__ __forceinline__ float rcpf(float x) { float r; asm("rcp.approx.ftz.f32 %0,%1;":"=f"(r):"f"(x)); return r; }

// ---------------------------------------------------------------------------
// Pass 1: f16x2 exps, fp32 binning (bit-identical to R16 => same histogram),
// then BLOCK-level aggregation: stage per-pixel bin bytes in smem, one warp
// aggregates each class over all 256 pixels into warp-private smem counters,
// and flushes ~20 REDs/class/block (vs ~48 with per-warp-only aggregation).
// ---------------------------------------------------------------------------
__global__ void __launch_bounds__(256) hist_kernel(
    const float* __restrict__ logits, const int* __restrict__ gt)
{
    const int tid  = threadIdx.x;
    const int lane = tid & 31;
    const int wid  = tid >> 5;

    int p  = blockIdx.x * blockDim.x + tid;          // grid exact: no tail
    int b  = p >> 18;
    int hw = p & (HW - 1);
    const float* base = logits + (size_t)b * CNUM * HW + hw;

    int lab = gt[p];
    bool valid = ((unsigned)lab < (unsigned)CNUM);
    int labx = valid ? lab : -1;

    const __half2 L2E2 = __float2half2_rn(1.4426950408889634f);

    __half2 e2[NPAIR];
    float S = 0.f;
    float elab = 0.f;
#pragma unroll
    for (int j = 0; j < NPAIR; j++) {
        float xa = __ldg(base + (size_t)(2 * j) * HW);
        float xb = (j < 9) ? __ldg(base + (size_t)(2 * j + 1) * HW)
                           : -1.0e4f;                // dummy: exp->0
        __half2 y = __hmul2(__floats2half2_rn(xa, xb), L2E2);
        __half2 ee = h2exp2(y);
        e2[j] = ee;
        float2 ef = __half22float2(ee);
        S += ef.x + ef.y;
        elab = (2 * j     == labx) ? ef.x : elab;    // bit-identical extraction
        elab = (2 * j + 1 == labx) ? ef.y : elab;
    }

    float rsn = rcpf(S) * (float)NB;                 // NB / S

    float pcl = elab * rsn;                          // fg bin (same rounding)
    int ig = (int)((float)NB - pcl);
    ig = ig < 0 ? 0 : ig;
    unsigned fgi = 40u + (unsigned)ig;               // [40,72], never 0

    // pack 19 per-class keys (byte each; 0 = non-emitting) into 5 words
    unsigned w[5] = {0u, 0u, 0u, 0u, 0u};
#pragma unroll
    for (int j = 0; j < NPAIR; j++) {
        float2 ef = __half22float2(e2[j]);
#pragma unroll
        for (int h = 0; h < 2; h++) {
            int c = 2 * j + h;
            if (c >= CNUM) break;                    // compile-time
            float pcN = (h ? ef.y : ef.x) * rsn;
            unsigned idx = (unsigned)pcN;            // [0,32]; 0 = dead bin
            idx = (c == labx) ? fgi : idx;
            unsigned key = valid ? idx : 0u;
            w[c >> 2] |= key << (8 * (c & 3));
        }
    }

    __shared__ unsigned stage[5 * 256];              // [word][pixel]
    __shared__ unsigned cnt[8][STRIDE];              // per-warp counters
#pragma unroll
    for (int k = 0; k < 5; k++) stage[k * 256 + tid] = w[k];
    __syncthreads();

    unsigned* gbase = g_hist + (size_t)(blockIdx.x & (NREP - 1)) * (CNUM * STRIDE);

    // each class handled by one warp over all 256 pixels
    for (int c = wid; c < CNUM; c += 8) {
        cnt[wid][lane] = 0u;
        cnt[wid][lane + 32] = 0u;
        if (lane < 16) cnt[wid][lane + 64] = 0u;
        __syncwarp();

        const int k  = c >> 2;
        const int sh = 8 * (c & 3);
        const unsigned* srow = stage + k * 256;
#pragma unroll
        for (int i = 0; i < 8; i++) {
            unsigned v = (srow[i * 32 + lane] >> sh) & 0xFFu;
            unsigned mask = __match_any_sync(0xFFFFFFFFu, v);
            bool leader = ((unsigned)lane == (unsigned)(__ffs(mask) - 1));
            if ((v != 0u) && leader)
                cnt[wid][v] += __popc(mask);         // one leader per v per i
        }
        __syncwarp();

        // flush nonzero counters (counter index == position in class row)
        unsigned a0 = cnt[wid][lane];
        unsigned a1 = cnt[wid][lane + 32];
        if (a0) atomicAdd(gbase + c * STRIDE + lane, a0);
        if (a1) atomicAdd(gbase + c * STRIDE + lane + 32, a1);
        if (lane < 16) {
            unsigned a2 = cnt[wid][lane + 64];
            if (a2) atomicAdd(gbase + c * STRIDE + lane + 64, a2);
        }
        __syncwarp();
    }
}

// ---------------------------------------------------------------------------
// Pass 2 (+fused finalize): one block per class, 128 threads (proven R13/R16).
// ---------------------------------------------------------------------------
__global__ void __launch_bounds__(128) loss_kernel(float* __restrict__ out) {
    const int c = blockIdx.x;
    const int t = threadIdx.x;

    __shared__ unsigned mg[STRIDE];
    __shared__ unsigned sU[33], sF[33];
    __shared__ float    red[32];
    __shared__ bool     amLast;

    if (t < STRIDE) {
        unsigned* cls = g_hist + (size_t)c * STRIDE;
        unsigned sum = 0;
#pragma unroll
        for (int r = 0; r < NREP; r++) {
            size_t idx = (size_t)r * (CNUM * STRIDE) + t;
            sum += cls[idx];
            cls[idx] = 0u;                    // restore zero-invariant
        }
        mg[t] = sum;
    }
    __syncthreads();

    if (t <= 32) {
        sU[t] = mg[t];                        // nonfg err bin t (bin 0 unused)
        sF[t] = mg[40 + t];                   // fg err bin t
    }
    __syncthreads();

    for (int off = 1; off < 33; off <<= 1) {
        unsigned u = 0, f = 0;
        if (t <= 32) {
            u = sU[t]; f = sF[t];
            if (t + off <= 32) { u += sU[t + off]; f += sF[t + off]; }
        }
        __syncthreads();
        if (t <= 32) { sU[t] = u; sF[t] = f; }
        __syncthreads();
    }

    unsigned gts = sF[0];
    float J = 0.f;
    if (t >= 1 && t < NB && gts > 0)
        J = 1.f - __fdividef((float)(gts - sF[t]), (float)(gts + sU[t]));
    if (t < 32) red[t] = J;
    __syncthreads();

    for (int off = 16; off > 0; off >>= 1) {
        if (t < off) red[t] += red[t + off];
        __syncthreads();
    }

    if (t == 0) {
        g_lossc[c] = (red[0] + 0.5f) * (1.0f / (float)NB);
        g_gts[c]   = gts;
        __threadfence();
        unsigned prev = atomicInc(&g_done, CNUM - 1);   // wraps to 0 at CNUM
        amLast = (prev == CNUM - 1);
    }
    __syncthreads();

    if (amLast && t == 0) {
        __threadfence();
        float s = 0.f; int np = 0;
#pragma unroll
        for (int k = 0; k < CNUM; k++) {
            if (g_gts[k] > 0u) { s += g_lossc[k]; np++; }
        }
        out[0] = s / (float)(np > 0 ? np : 1);
    }
}

// ---------------------------------------------------------------------------
extern "C" void kernel_launch(void* const* d_in, const int* in_sizes, int n_in,
                              void* d_out, int out_size)
{
    const float* logits = (const float*)d_in[0];
    const int*   gt     = (const int*)d_in[1];
    float*       out    = (float*)d_out;

    hist_kernel<<<PTOT / 256, 256>>>(logits, gt);
    loss_kernel<<<CNUM, 128>>>(out);
}